// round 3
// baseline (speedup 1.0000x reference)
#include <cuda_runtime.h>
#include <math_constants.h>

// Problem constants (fixed by the dataset: B=2, H=96, W=96, P=32)
#define NTHREADS 256
#define PMAX 32

// Scratch (allocation-free rule: __device__ globals)
__device__ float g_zfeat[256];
__device__ float g_W2T[32 * 256];    // W2T[c][o] = W2[o][c]
__device__ float g_W3T[256 * 256];   // W3T[c][o] = W3[o][c]

// ---------------------------------------------------------------------------
// Prep 1: transpose W2 and W3 so main-kernel weight loads are coalesced.
// grid 256 x block 256
// ---------------------------------------------------------------------------
__global__ void prep_transpose(const float* __restrict__ W2,
                               const float* __restrict__ W3) {
    const int o = threadIdx.x;   // 0..255
    const int c = blockIdx.x;    // 0..255
    g_W3T[c * 256 + o] = W3[o * 256 + c];
    if (c < 32) g_W2T[c * 256 + o] = W2[o * 32 + c];
}

// ---------------------------------------------------------------------------
// Prep 2: zfeat = pointnet(single all-zero point). 1 block x 256 threads.
// h1 = relu(b1); h2 = relu(W2 h1 + b2); zfeat = W3 h2 + b3
// ---------------------------------------------------------------------------
__global__ void prep_zfeat(const float* __restrict__ b1,
                           const float* __restrict__ W2,
                           const float* __restrict__ b2,
                           const float* __restrict__ W3,
                           const float* __restrict__ b3) {
    __shared__ float h1[32];
    __shared__ float h2[256];
    const int t = threadIdx.x;
    if (t < 32) h1[t] = fmaxf(b1[t], 0.0f);
    __syncthreads();
    float a = b2[t];
#pragma unroll 8
    for (int c = 0; c < 32; c++) a += W2[t * 32 + c] * h1[c];
    h2[t] = fmaxf(a, 0.0f);
    __syncthreads();
    float o = b3[t];
#pragma unroll 8
    for (int c = 0; c < 256; c++) o += W3[t * 256 + c] * h2[c];
    g_zfeat[t] = o;
}

// ---------------------------------------------------------------------------
// Main kernel: one CTA per voxel, 256 threads = 256 output channels.
// Computes the full MLP only for the `num` valid points; max-pools; adds b3
// once (bias commutes with max). Empty voxels copy precomputed zfeat.
// ---------------------------------------------------------------------------
__global__ void __launch_bounds__(NTHREADS)
voxel_kernel(const float* __restrict__ fv,     // [V][32][3]
             const int*   __restrict__ fvnum,  // [V]
             const float* __restrict__ W1,     // [32][3]
             const float* __restrict__ b1,     // [32]
             const float* __restrict__ b2,     // [256]
             const float* __restrict__ b3,     // [256]
             float* __restrict__ out)          // [V][256]
{
    const int v = blockIdx.x;
    const int t = threadIdx.x;
    const int num = fvnum[v];

    if (num == 0) {                       // uniform branch per CTA
        out[(size_t)v * 256 + t] = g_zfeat[t];
        return;
    }

    __shared__ float pts[96];             // 32 points x 3
    __shared__ float w1s[96];
    __shared__ float b1s[32];
    __shared__ float h1s[PMAX][32];       // layer-1 activations
    __shared__ float h2s[PMAX][256];      // layer-2 activations (p-major)

    if (t < 96) {
        pts[t] = fv[(size_t)v * 96 + t];
        w1s[t] = W1[t];
    } else if (t < 128) {
        b1s[t - 96] = b1[t - 96];
    }
    __syncthreads();

    // ---- layer 1: h1[p][k] = relu(W1[k]·x[p] + b1[k]), valid points only ----
    for (int idx = t; idx < num * 32; idx += NTHREADS) {
        const int p = idx >> 5;
        const int k = idx & 31;
        float a = b1s[k]
                + w1s[k * 3 + 0] * pts[p * 3 + 0]
                + w1s[k * 3 + 1] * pts[p * 3 + 1]
                + w1s[k * 3 + 2] * pts[p * 3 + 2];
        h1s[p][k] = fmaxf(a, 0.0f);
    }
    __syncthreads();

    // ---- layer 2: thread t = channel; W2 column t in registers (coalesced).
    //      h1 row read as float4 broadcasts (8 LDS instead of 32). ----
    {
        float w[32];
#pragma unroll
        for (int c = 0; c < 32; c++) w[c] = g_W2T[c * 256 + t];
        const float bo = __ldg(&b2[t]);
        for (int p = 0; p < num; p++) {
            float a = bo;
#pragma unroll
            for (int c4 = 0; c4 < 8; c4++) {
                const float4 h = *(const float4*)&h1s[p][c4 * 4];
                a += w[c4 * 4 + 0] * h.x;
                a += w[c4 * 4 + 1] * h.y;
                a += w[c4 * 4 + 2] * h.z;
                a += w[c4 * 4 + 3] * h.w;
            }
            h2s[p][t] = fmaxf(a, 0.0f);   // conflict-free (consecutive banks)
        }
    }
    __syncthreads();

    // ---- layer 3 + max-pool: 16-point groups (one W3T pass covers 16 pts,
    //      halving L2 weight traffic vs 8-pt groups), coalesced W3T loads ----
    float m = -CUDART_INF_F;
    const float* w3t = g_W3T + t;
    const int ngroups = (num + 15) >> 4;
    for (int g = 0; g < ngroups; g++) {
        const int pbase = g << 4;
        float acc[16];
#pragma unroll
        for (int i = 0; i < 16; i++) acc[i] = 0.0f;
#pragma unroll 2
        for (int c4 = 0; c4 < 64; c4++) {
            // 4 coalesced scalar weight loads (warp reads 128B contiguous)
            const float wa = __ldg(&w3t[(c4 * 4 + 0) * 256]);
            const float wb = __ldg(&w3t[(c4 * 4 + 1) * 256]);
            const float wc = __ldg(&w3t[(c4 * 4 + 2) * 256]);
            const float wd = __ldg(&w3t[(c4 * 4 + 3) * 256]);
#pragma unroll
            for (int i = 0; i < 16; i++) {
                // broadcast float4 LDS (same address across the warp)
                const float4 h = *(const float4*)&h2s[pbase + i][c4 * 4];
                acc[i] += wa * h.x;
                acc[i] += wb * h.y;
                acc[i] += wc * h.z;
                acc[i] += wd * h.w;
            }
        }
        // masked max: padded lanes may hold garbage (uninit smem) — never used
#pragma unroll
        for (int i = 0; i < 16; i++)
            if (pbase + i < num) m = fmaxf(m, acc[i]);
    }

    out[(size_t)v * 256 + t] = m + __ldg(&b3[t]);
}

// ---------------------------------------------------------------------------
// Launch. Inputs (metadata order): Frustum_Voxel, Frustum_Voxel_num,
// W1, b1, W2, b2, W3, b3. Output: [B,H,W,256] float32.
// ---------------------------------------------------------------------------
extern "C" void kernel_launch(void* const* d_in, const int* in_sizes, int n_in,
                              void* d_out, int out_size) {
    const float* fv    = (const float*)d_in[0];
    const int*   fvnum = (const int*)  d_in[1];
    const float* W1    = (const float*)d_in[2];
    const float* b1    = (const float*)d_in[3];
    const float* W2    = (const float*)d_in[4];
    const float* b2    = (const float*)d_in[5];
    const float* W3    = (const float*)d_in[6];
    const float* b3    = (const float*)d_in[7];
    float* out = (float*)d_out;

    const int V = in_sizes[1];  // number of voxels (B*H*W)

    prep_transpose<<<256, 256>>>(W2, W3);
    prep_zfeat<<<1, 256>>>(b1, W2, b2, W3, b3);
    voxel_kernel<<<V, NTHREADS>>>(fv, fvnum, W1, b1, b2, b3, out);
}

// round 4
// speedup vs baseline: 1.1136x; 1.1136x over previous
#include <cuda_runtime.h>
#include <math_constants.h>
#include <cstdint>

// Problem constants (fixed by dataset: B=2, H=96, W=96, P=32)
#define NTHREADS 256
#define H2S 268   // h2 smem row stride (floats): conflict-free A-fragment loads
#define BSS 264   // B  smem row stride (floats): conflict-free B-fragment loads

// Scratch (allocation-free rule: __device__ globals)
__device__ float g_zfeat[256];
__device__ float g_W2T[32 * 256];    // W2T[c][o] = W2[o][c]
__device__ float g_W3T[256 * 256];   // W3T[k][n] = W3[n][k]  (GEMM B matrix)

// ---------------------------------------------------------------------------
// Prep 1: transpose W2 and W3. grid 256 x block 256
// ---------------------------------------------------------------------------
__global__ void prep_transpose(const float* __restrict__ W2,
                               const float* __restrict__ W3) {
    const int o = threadIdx.x;   // 0..255
    const int c = blockIdx.x;    // 0..255
    g_W3T[c * 256 + o] = W3[o * 256 + c];
    if (c < 32) g_W2T[c * 256 + o] = W2[o * 32 + c];
}

// ---------------------------------------------------------------------------
// Prep 2: zfeat = pointnet(single all-zero point). 1 block x 256 threads.
// ---------------------------------------------------------------------------
__global__ void prep_zfeat(const float* __restrict__ b1,
                           const float* __restrict__ W2,
                           const float* __restrict__ b2,
                           const float* __restrict__ W3,
                           const float* __restrict__ b3) {
    __shared__ float h1[32];
    __shared__ float h2[256];
    const int t = threadIdx.x;
    if (t < 32) h1[t] = fmaxf(b1[t], 0.0f);
    __syncthreads();
    float a = b2[t];
#pragma unroll 8
    for (int c = 0; c < 32; c++) a += W2[t * 32 + c] * h1[c];
    h2[t] = fmaxf(a, 0.0f);
    __syncthreads();
    float o = b3[t];
#pragma unroll 8
    for (int c = 0; c < 256; c++) o += W3[t * 256 + c] * h2[c];
    g_zfeat[t] = o;
}

// ---------------------------------------------------------------------------
// tf32 helpers: split fp32 into hi (top 10 mantissa bits, exact under mask)
// and lo (exact residual). 3xTF32: Ah*Bh + Al*Bh + Ah*Bl ~ fp32 accuracy.
// ---------------------------------------------------------------------------
__device__ __forceinline__ uint32_t tf32_hi(float x) {
    return __float_as_uint(x) & 0xFFFFE000u;
}
__device__ __forceinline__ uint32_t tf32_lo(float x, uint32_t hi_bits) {
    return __float_as_uint(x - __uint_as_float(hi_bits));
}

__device__ __forceinline__ void mma_tf32(float* d,
                                         uint32_t a0, uint32_t a1,
                                         uint32_t a2, uint32_t a3,
                                         uint32_t b0, uint32_t b1) {
    asm volatile(
        "mma.sync.aligned.m16n8k8.row.col.f32.tf32.tf32.f32 "
        "{%0,%1,%2,%3},{%4,%5,%6,%7},{%8,%9},{%0,%1,%2,%3};"
        : "+f"(d[0]), "+f"(d[1]), "+f"(d[2]), "+f"(d[3])
        : "r"(a0), "r"(a1), "r"(a2), "r"(a3), "r"(b0), "r"(b1));
}

// ---------------------------------------------------------------------------
// Main kernel: one CTA per 2 voxels. Layers 1-2 on CUDA cores (valid points
// only, invalid h2 rows zeroed). Layer 3 = [64 x 256] x [256 x 256] GEMM on
// tensor cores (3xTF32). Max-pool + b3 / zfeat epilogue.
// Dynamic smem layout (floats):
//   [0)      pts   192
//   [192)    w1s    96
//   [288)    b1s    32
//   [320)    h2s   64*H2S
//   [320+..) bss   64*BSS   (B chunk; overlaid: h1s [64][36] before GEMM,
//                            C [64][BSS] after GEMM)
// ---------------------------------------------------------------------------
__global__ void __launch_bounds__(NTHREADS)
voxel_tc_kernel(const float* __restrict__ fv,     // [V][32][3]
                const int*   __restrict__ fvnum,  // [V]
                const float* __restrict__ W1,     // [32][3]
                const float* __restrict__ b1,     // [32]
                const float* __restrict__ b2,     // [256]
                const float* __restrict__ b3,     // [256]
                float* __restrict__ out)          // [V][256]
{
    extern __shared__ float sm[];
    float* pts = sm;                       // 192
    float* w1s = sm + 192;                 // 96
    float* b1s = sm + 288;                 // 32
    float* h2s = sm + 320;                 // 64*H2S
    float* bss = sm + 320 + 64 * H2S;      // 64*BSS
    float* h1s = bss;                      // overlay [64][36]

    const int t = threadIdx.x;
    const int v0 = blockIdx.x * 2;
    const int num0 = fvnum[v0];
    const int num1 = fvnum[v0 + 1];

    if ((num0 | num1) != 0) {
        // ---- stage points + layer-1 weights ----
        if (t < 192) pts[t] = fv[(size_t)v0 * 96 + t];
        if (t < 96)  w1s[t] = W1[t];
        if (t >= 96 && t < 128) b1s[t - 96] = b1[t - 96];
        __syncthreads();

        // ---- layer 1: all 64 points (trivial cost) ----
        for (int idx = t; idx < 64 * 32; idx += NTHREADS) {
            const int p = idx >> 5;
            const int k = idx & 31;
            float a = b1s[k]
                    + w1s[k * 3 + 0] * pts[p * 3 + 0]
                    + w1s[k * 3 + 1] * pts[p * 3 + 1]
                    + w1s[k * 3 + 2] * pts[p * 3 + 2];
            h1s[p * 36 + k] = fmaxf(a, 0.0f);
        }
        __syncthreads();

        // ---- layer 2: thread t = channel; valid rows only, others zeroed ----
        {
            float w[32];
#pragma unroll
            for (int c = 0; c < 32; c++) w[c] = g_W2T[c * 256 + t];
            const float bo = __ldg(&b2[t]);
            for (int p = 0; p < 64; p++) {
                const bool valid = (p < 32) ? (p < num0) : (p - 32 < num1);
                if (valid) {
                    float a = bo;
#pragma unroll
                    for (int c4 = 0; c4 < 8; c4++) {
                        const float4 h = *(const float4*)&h1s[p * 36 + c4 * 4];
                        a += w[c4 * 4 + 0] * h.x;
                        a += w[c4 * 4 + 1] * h.y;
                        a += w[c4 * 4 + 2] * h.z;
                        a += w[c4 * 4 + 3] * h.w;
                    }
                    h2s[p * H2S + t] = fmaxf(a, 0.0f);
                } else {
                    h2s[p * H2S + t] = 0.0f;   // GEMM-safe padding
                }
            }
        }

        // ---- layer 3: C[64][256] = h2[64][256] @ W3T[256][256], 3xTF32 ----
        const int lane = t & 31;
        const int warp = t >> 5;
        const int mg = warp & 3;            // M group: rows mg*16..+15
        const int ng = warp >> 2;           // N group: cols ng*128..+127
        const int arow = mg * 16 + (lane >> 2);

        float acc[16][4];
#pragma unroll
        for (int i = 0; i < 16; i++)
#pragma unroll
            for (int j = 0; j < 4; j++) acc[i][j] = 0.0f;

        for (int kc = 0; kc < 4; kc++) {
            __syncthreads();   // bss reuse (h1 overlay / prev chunk consumed)
            // cooperative, coalesced stage of B chunk: W3T rows kc*64..+63
            for (int idx = t; idx < 64 * 64; idx += NTHREADS) {
                const int row = idx >> 6;
                const int c4  = idx & 63;
                const float4 wv =
                    *(const float4*)&g_W3T[(kc * 64 + row) * 256 + c4 * 4];
                *(float4*)&bss[row * BSS + c4 * 4] = wv;
            }
            __syncthreads();

#pragma unroll
            for (int k8 = 0; k8 < 8; k8++) {
                const int kl = k8 * 8 + (lane & 3);    // k within chunk
                const int kg = kc * 64 + kl;           // global k
                const float a0 = h2s[arow * H2S + kg];
                const float a1 = h2s[(arow + 8) * H2S + kg];
                const float a2 = h2s[arow * H2S + kg + 4];
                const float a3 = h2s[(arow + 8) * H2S + kg + 4];
                const uint32_t ah0 = tf32_hi(a0), al0 = tf32_lo(a0, ah0);
                const uint32_t ah1 = tf32_hi(a1), al1 = tf32_lo(a1, ah1);
                const uint32_t ah2 = tf32_hi(a2), al2 = tf32_lo(a2, ah2);
                const uint32_t ah3 = tf32_hi(a3), al3 = tf32_lo(a3, ah3);

                const float* brow0 = &bss[kl * BSS + ng * 128 + (lane >> 2)];
                const float* brow1 = brow0 + 4 * BSS;
#pragma unroll
                for (int n8 = 0; n8 < 16; n8++) {
                    const float b0 = brow0[n8 * 8];
                    const float b1v = brow1[n8 * 8];
                    const uint32_t bh0 = tf32_hi(b0),  bl0 = tf32_lo(b0, bh0);
                    const uint32_t bh1 = tf32_hi(b1v), bl1 = tf32_lo(b1v, bh1);
                    mma_tf32(acc[n8], ah0, ah1, ah2, ah3, bh0, bh1);
                    mma_tf32(acc[n8], al0, al1, al2, al3, bh0, bh1);
                    mma_tf32(acc[n8], ah0, ah1, ah2, ah3, bl0, bl1);
                }
            }
        }
        __syncthreads();

        // ---- store C fragments into bss (reused as C [64][BSS]) ----
#pragma unroll
        for (int n8 = 0; n8 < 16; n8++) {
            const int col = ng * 128 + n8 * 8 + (lane & 3) * 2;
            *(float2*)&bss[arow * BSS + col] =
                make_float2(acc[n8][0], acc[n8][1]);
            *(float2*)&bss[(arow + 8) * BSS + col] =
                make_float2(acc[n8][2], acc[n8][3]);
        }
        __syncthreads();
    }

    // ---- epilogue: per-voxel masked max + b3, or zfeat for empty ----
#pragma unroll
    for (int v = 0; v < 2; v++) {
        const int nv = v ? num1 : num0;
        float r;
        if (nv == 0) {
            r = g_zfeat[t];
        } else {
            float m = -CUDART_INF_F;
            const float* c = &bss[v * 32 * BSS + t];
            for (int p = 0; p < nv; p++) m = fmaxf(m, c[p * BSS]);
            r = m + __ldg(&b3[t]);
        }
        out[(size_t)(v0 + v) * 256 + t] = r;
    }
}

// ---------------------------------------------------------------------------
// Launch. Inputs: Frustum_Voxel, Frustum_Voxel_num, W1,b1,W2,b2,W3,b3.
// ---------------------------------------------------------------------------
extern "C" void kernel_launch(void* const* d_in, const int* in_sizes, int n_in,
                              void* d_out, int out_size) {
    const float* fv    = (const float*)d_in[0];
    const int*   fvnum = (const int*)  d_in[1];
    const float* W1    = (const float*)d_in[2];
    const float* b1    = (const float*)d_in[3];
    const float* W2    = (const float*)d_in[4];
    const float* b2    = (const float*)d_in[5];
    const float* W3    = (const float*)d_in[6];
    const float* b3    = (const float*)d_in[7];
    float* out = (float*)d_out;

    const int V = in_sizes[1];                  // 18432 voxels (even)
    const int smem_bytes = (320 + 64 * H2S + 64 * BSS) * 4;   // 137472

    static bool attr_set = false;
    if (!attr_set) {
        cudaFuncSetAttribute(voxel_tc_kernel,
                             cudaFuncAttributeMaxDynamicSharedMemorySize,
                             smem_bytes);
        attr_set = true;
    }

    prep_transpose<<<256, 256>>>(W2, W3);
    prep_zfeat<<<1, 256>>>(b1, W2, b2, W3, b3);
    voxel_tc_kernel<<<V / 2, NTHREADS, smem_bytes>>>(fv, fvnum, W1, b1, b2, b3,
                                                     out);
}

// round 6
// speedup vs baseline: 1.7804x; 1.5988x over previous
#include <cuda_runtime.h>
#include <math_constants.h>
#include <cstdint>

// Problem constants (fixed by dataset: B=2, H=96, W=96, P=32)
#define NTHREADS 256
#define H2S 268   // h2 smem row stride (floats): conflict-free A-fragment loads
#define BSS 264   // B  smem row stride (floats): conflict-free B-fragment loads

// Scratch (allocation-free rule: __device__ globals)
__device__ float g_zfeat[256];
__device__ float g_W2T[32 * 256];    // W2T[c][o] = W2[o][c]            (fp32)
__device__ float g_W3T[256 * 256];   // W3T[k][n] = W3[n][k], tf32-rounded

__device__ __forceinline__ float to_tf32_rn(float x) {
    uint32_t r;
    asm("cvt.rna.tf32.f32 %0, %1;" : "=r"(r) : "f"(x));
    return __uint_as_float(r);
}

// ---------------------------------------------------------------------------
// Prep (single kernel, grid 257 x 256):
//   blocks 0..255: transpose W2 (fp32) and W3 (rounded to tf32-rn, so the
//                  GEMM gets round-to-nearest instead of biased truncation)
//   block 256:     zfeat = pointnet(zero point), full fp32
// ---------------------------------------------------------------------------
__global__ void prep_kernel(const float* __restrict__ W2,
                            const float* __restrict__ W3,
                            const float* __restrict__ b1,
                            const float* __restrict__ b2,
                            const float* __restrict__ b3) {
    const int t = threadIdx.x;
    const int blk = blockIdx.x;
    if (blk < 256) {
        const int c = blk;                    // input channel (k)
        g_W3T[c * 256 + t] = to_tf32_rn(W3[t * 256 + c]);
        if (c < 32) g_W2T[c * 256 + t] = W2[t * 32 + c];
    } else {
        __shared__ float h1[32];
        __shared__ float h2[256];
        if (t < 32) h1[t] = fmaxf(b1[t], 0.0f);
        __syncthreads();
        float a = b2[t];
#pragma unroll 8
        for (int c = 0; c < 32; c++) a += W2[t * 32 + c] * h1[c];
        h2[t] = fmaxf(a, 0.0f);
        __syncthreads();
        float o = b3[t];
#pragma unroll 8
        for (int c = 0; c < 256; c++) o += W3[t * 256 + c] * h2[c];
        g_zfeat[t] = o;
    }
}

__device__ __forceinline__ void mma_tf32(float* d,
                                         uint32_t a0, uint32_t a1,
                                         uint32_t a2, uint32_t a3,
                                         uint32_t b0, uint32_t b1) {
    asm volatile(
        "mma.sync.aligned.m16n8k8.row.col.f32.tf32.tf32.f32 "
        "{%0,%1,%2,%3},{%4,%5,%6,%7},{%8,%9},{%0,%1,%2,%3};"
        : "+f"(d[0]), "+f"(d[1]), "+f"(d[2]), "+f"(d[3])
        : "r"(a0), "r"(a1), "r"(a2), "r"(a3), "r"(b0), "r"(b1));
}

// ---------------------------------------------------------------------------
// Main kernel: one CTA per 2 voxels. Layers 1-2 on CUDA cores (valid rows,
// invalid h2 rows zeroed). Layer 3 = [64x256]x[256x256] GEMM, 1xTF32-RN,
// with per-warp skip of all-padding 16-row M tiles. Max-pool + b3 epilogue.
// ---------------------------------------------------------------------------
__global__ void __launch_bounds__(NTHREADS)
voxel_tc_kernel(const float* __restrict__ fv,     // [V][32][3]
                const int*   __restrict__ fvnum,  // [V]
                const float* __restrict__ W1,     // [32][3]
                const float* __restrict__ b1,     // [32]
                const float* __restrict__ b2,     // [256]
                const float* __restrict__ b3,     // [256]
                float* __restrict__ out)          // [V][256]
{
    extern __shared__ float sm[];
    float* pts = sm;                       // 192
    float* w1s = sm + 192;                 // 96
    float* b1s = sm + 288;                 // 32
    float* h2s = sm + 320;                 // 64*H2S
    float* bss = sm + 320 + 64 * H2S;      // 64*BSS (B chunk; h1/C overlay)
    float* h1s = bss;                      // overlay [64][36]

    const int t = threadIdx.x;
    const int v0 = blockIdx.x * 2;
    const int num0 = fvnum[v0];
    const int num1 = fvnum[v0 + 1];

    if ((num0 | num1) != 0) {
        // ---- stage points + layer-1 weights ----
        if (t < 192) pts[t] = fv[(size_t)v0 * 96 + t];
        if (t < 96)  w1s[t] = W1[t];
        if (t >= 96 && t < 128) b1s[t - 96] = b1[t - 96];
        __syncthreads();

        // ---- layer 1: all 64 points (trivial cost) ----
        for (int idx = t; idx < 64 * 32; idx += NTHREADS) {
            const int p = idx >> 5;
            const int k = idx & 31;
            float a = b1s[k]
                    + w1s[k * 3 + 0] * pts[p * 3 + 0]
                    + w1s[k * 3 + 1] * pts[p * 3 + 1]
                    + w1s[k * 3 + 2] * pts[p * 3 + 2];
            h1s[p * 36 + k] = fmaxf(a, 0.0f);
        }
        __syncthreads();

        // ---- layer 2: thread t = channel; valid rows only, others zeroed ----
        {
            float w[32];
#pragma unroll
            for (int c = 0; c < 32; c++) w[c] = g_W2T[c * 256 + t];
            const float bo = __ldg(&b2[t]);
            for (int p = 0; p < 64; p++) {
                const bool valid = (p < 32) ? (p < num0) : (p - 32 < num1);
                if (valid) {
                    float a = bo;
#pragma unroll
                    for (int c4 = 0; c4 < 8; c4++) {
                        const float4 h = *(const float4*)&h1s[p * 36 + c4 * 4];
                        a += w[c4 * 4 + 0] * h.x;
                        a += w[c4 * 4 + 1] * h.y;
                        a += w[c4 * 4 + 2] * h.z;
                        a += w[c4 * 4 + 3] * h.w;
                    }
                    h2s[p * H2S + t] = fmaxf(a, 0.0f);
                } else {
                    h2s[p * H2S + t] = 0.0f;   // GEMM-safe padding
                }
            }
        }

        // ---- layer 3: C[64][256] = h2 @ W3T, 1xTF32 (RN-rounded inputs) ----
        const int lane = t & 31;
        const int warp = t >> 5;
        const int mg = warp & 3;            // M tile: rows mg*16..+15
        const int ng = warp >> 2;           // N half: cols ng*128..+127
        const int arow = mg * 16 + (lane >> 2);

        // Tile liveness: rows of tile mg are voxel (mg>=2), local points
        // [(mg&1)*16, +16). Tile is all-padding iff num <= local start.
        const int my_num = (mg >= 2) ? num1 : num0;
        const bool tile_live = my_num > ((mg & 1) * 16);

        float acc[16][4];
#pragma unroll
        for (int i = 0; i < 16; i++)
#pragma unroll
            for (int j = 0; j < 4; j++) acc[i][j] = 0.0f;

        for (int kc = 0; kc < 4; kc++) {
            __syncthreads();   // bss reuse (h1 overlay / prev chunk consumed)
            // cooperative, coalesced stage of B chunk: W3T rows kc*64..+63
            for (int idx = t; idx < 64 * 64; idx += NTHREADS) {
                const int row = idx >> 6;
                const int c4  = idx & 63;
                const float4 wv =
                    *(const float4*)&g_W3T[(kc * 64 + row) * 256 + c4 * 4];
                *(float4*)&bss[row * BSS + c4 * 4] = wv;
            }
            __syncthreads();

            if (!tile_live) continue;       // skip MMAs for all-padding tile

#pragma unroll
            for (int k8 = 0; k8 < 8; k8++) {
                const int kl = k8 * 8 + (lane & 3);    // k within chunk
                const int kg = kc * 64 + kl;           // global k
                const uint32_t a0 =
                    __float_as_uint(to_tf32_rn(h2s[arow * H2S + kg]));
                const uint32_t a1 =
                    __float_as_uint(to_tf32_rn(h2s[(arow + 8) * H2S + kg]));
                const uint32_t a2 =
                    __float_as_uint(to_tf32_rn(h2s[arow * H2S + kg + 4]));
                const uint32_t a3 =
                    __float_as_uint(to_tf32_rn(h2s[(arow + 8) * H2S + kg + 4]));

                const float* brow0 = &bss[kl * BSS + ng * 128 + (lane >> 2)];
                const float* brow1 = brow0 + 4 * BSS;
#pragma unroll
                for (int n8 = 0; n8 < 16; n8++) {
                    const uint32_t b0 = __float_as_uint(brow0[n8 * 8]);
                    const uint32_t b1v = __float_as_uint(brow1[n8 * 8]);
                    mma_tf32(acc[n8], a0, a1, a2, a3, b0, b1v);
                }
            }
        }
        __syncthreads();

        // ---- store C fragments into bss (reused as C [64][BSS]) ----
#pragma unroll
        for (int n8 = 0; n8 < 16; n8++) {
            const int col = ng * 128 + n8 * 8 + (lane & 3) * 2;
            *(float2*)&bss[arow * BSS + col] =
                make_float2(acc[n8][0], acc[n8][1]);
            *(float2*)&bss[(arow + 8) * BSS + col] =
                make_float2(acc[n8][2], acc[n8][3]);
        }
        __syncthreads();
    }

    // ---- epilogue: per-voxel masked max + b3, or zfeat for empty ----
#pragma unroll
    for (int v = 0; v < 2; v++) {
        const int nv = v ? num1 : num0;
        float r;
        if (nv == 0) {
            r = g_zfeat[t];
        } else {
            float m = -CUDART_INF_F;
            const float* c = &bss[v * 32 * BSS + t];
            for (int p = 0; p < nv; p++) m = fmaxf(m, c[p * BSS]);
            r = m + __ldg(&b3[t]);
        }
        out[(size_t)(v0 + v) * 256 + t] = r;
    }
}

// ---------------------------------------------------------------------------
// Launch. Inputs: Frustum_Voxel, Frustum_Voxel_num, W1,b1,W2,b2,W3,b3.
// Launch period is 2 (prep, main), so ncu -s 5 -c 1 captures the MAIN kernel.
// ---------------------------------------------------------------------------
extern "C" void kernel_launch(void* const* d_in, const int* in_sizes, int n_in,
                              void* d_out, int out_size) {
    const float* fv    = (const float*)d_in[0];
    const int*   fvnum = (const int*)  d_in[1];
    const float* W1    = (const float*)d_in[2];
    const float* b1    = (const float*)d_in[3];
    const float* W2    = (const float*)d_in[4];
    const float* b2    = (const float*)d_in[5];
    const float* W3    = (const float*)d_in[6];
    const float* b3    = (const float*)d_in[7];
    float* out = (float*)d_out;

    const int V = in_sizes[1];                  // 18432 voxels (even)
    const int smem_bytes = (320 + 64 * H2S + 64 * BSS) * 4;   // 137472

    static bool attr_set = false;
    if (!attr_set) {
        cudaFuncSetAttribute(voxel_tc_kernel,
                             cudaFuncAttributeMaxDynamicSharedMemorySize,
                             smem_bytes);
        attr_set = true;
    }

    prep_kernel<<<257, 256>>>(W2, W3, b1, b2, b3);
    voxel_tc_kernel<<<V / 2, NTHREADS, smem_bytes>>>(fv, fvnum, W1, b1, b2, b3,
                                                     out);
}

// round 7
// speedup vs baseline: 2.6086x; 1.4651x over previous
#include <cuda_runtime.h>
#include <math_constants.h>
#include <cstdint>

// Problem constants (fixed by dataset: B=2, H=96, W=96, P=32)
#define NTHREADS 256
#define H2S 268   // h2/C smem row stride (floats): conflict-free frag access
#define BSS 264   // B  smem row stride (floats): conflict-free frag access
#define H1S 36    // h1 smem row stride

// Scratch (allocation-free rule: __device__ globals)
__device__ float g_zfeat[256];
__device__ float g_W2T[32 * 256];    // W2T[c][o] = W2[o][c]            (fp32)
__device__ float g_W3T[256 * 256];   // W3T[k][n] = W3[n][k], tf32-rounded

__device__ __forceinline__ float to_tf32_rn(float x) {
    uint32_t r;
    asm("cvt.rna.tf32.f32 %0, %1;" : "=r"(r) : "f"(x));
    return __uint_as_float(r);
}
__device__ __forceinline__ uint32_t tf32_hi(float x) {
    return __float_as_uint(x) & 0xFFFFE000u;   // exact truncation split
}
__device__ __forceinline__ uint32_t tf32_lo(float x, uint32_t hi) {
    return __float_as_uint(x - __uint_as_float(hi));
}

// ---------------------------------------------------------------------------
// Prep (grid 257 x 256): transpose W2 (fp32) + W3 (tf32-rn); block 256: zfeat.
// ---------------------------------------------------------------------------
__global__ void prep_kernel(const float* __restrict__ W2,
                            const float* __restrict__ W3,
                            const float* __restrict__ b1,
                            const float* __restrict__ b2,
                            const float* __restrict__ b3) {
    const int t = threadIdx.x;
    const int blk = blockIdx.x;
    if (blk < 256) {
        const int c = blk;
        g_W3T[c * 256 + t] = to_tf32_rn(W3[t * 256 + c]);
        if (c < 32) g_W2T[c * 256 + t] = W2[t * 32 + c];
    } else {
        __shared__ float h1[32];
        __shared__ float h2[256];
        if (t < 32) h1[t] = fmaxf(b1[t], 0.0f);
        __syncthreads();
        float a = b2[t];
#pragma unroll 8
        for (int c = 0; c < 32; c++) a += W2[t * 32 + c] * h1[c];
        h2[t] = fmaxf(a, 0.0f);
        __syncthreads();
        float o = b3[t];
#pragma unroll 8
        for (int c = 0; c < 256; c++) o += W3[t * 256 + c] * h2[c];
        g_zfeat[t] = o;
    }
}

__device__ __forceinline__ void mma_tf32(float* d,
                                         uint32_t a0, uint32_t a1,
                                         uint32_t a2, uint32_t a3,
                                         uint32_t b0, uint32_t b1) {
    asm volatile(
        "mma.sync.aligned.m16n8k8.row.col.f32.tf32.tf32.f32 "
        "{%0,%1,%2,%3},{%4,%5,%6,%7},{%8,%9},{%0,%1,%2,%3};"
        : "+f"(d[0]), "+f"(d[1]), "+f"(d[2]), "+f"(d[3])
        : "r"(a0), "r"(a1), "r"(a2), "r"(a3), "r"(b0), "r"(b1));
}

// ---------------------------------------------------------------------------
// Main: one CTA / 2 voxels; 2 CTAs per SM (114 KB smem, <=128 regs).
// Warp tile: M=32 (one voxel) x N=64. Layer 2 = 3xTF32 MMA (fp32-grade).
// Layer 3 = 1xTF32-RN MMA, 8 K-chunks of 32, per-voxel + sub-tile skip.
// Smem (floats): pts 192 | w1s 96 | b1s 32 | b2s 256 | h1s 64*H1S |
//                h2s 64*H2S (C overlay after GEMM) | bss 32*BSS
// ---------------------------------------------------------------------------
__global__ void __launch_bounds__(NTHREADS, 2)
voxel_tc_kernel(const float* __restrict__ fv,     // [V][32][3]
                const int*   __restrict__ fvnum,  // [V]
                const float* __restrict__ W1,     // [32][3]
                const float* __restrict__ b1,     // [32]
                const float* __restrict__ b2,     // [256]
                const float* __restrict__ b3,     // [256]
                float* __restrict__ out)          // [V][256]
{
    extern __shared__ float sm[];
    float* pts = sm;                        // 192
    float* w1s = sm + 192;                  // 96
    float* b1s = sm + 288;                  // 32
    float* b2s = sm + 320;                  // 256
    float* h1s = sm + 576;                  // 64*H1S
    float* h2s = sm + 576 + 64 * H1S;       // 64*H2S (later: C)
    float* bss = sm + 576 + 64 * H1S + 64 * H2S;   // 32*BSS

    const int t = threadIdx.x;
    const int lane = t & 31;
    const int warp = t >> 5;
    const int v0 = blockIdx.x * 2;
    const int num0 = fvnum[v0];
    const int num1 = fvnum[v0 + 1];

    if ((num0 | num1) != 0) {
        // ---- stage points, layer-1 weights, biases ----
        if (t < 192) pts[t] = fv[(size_t)v0 * 96 + t];
        if (t < 96)  w1s[t] = W1[t];
        if (t >= 96 && t < 128) b1s[t - 96] = b1[t - 96];
        b2s[t] = b2[t];
        __syncthreads();

        // ---- layer 1: all 64 rows (finite garbage in invalid rows is OK;
        //      those C rows are masked at the pool) ----
        for (int idx = t; idx < 64 * 32; idx += NTHREADS) {
            const int p = idx >> 5;
            const int k = idx & 31;
            float a = b1s[k]
                    + w1s[k * 3 + 0] * pts[p * 3 + 0]
                    + w1s[k * 3 + 1] * pts[p * 3 + 1]
                    + w1s[k * 3 + 2] * pts[p * 3 + 2];
            h1s[p * H1S + k] = fmaxf(a, 0.0f);
        }
        // ---- stage W2T [32][256] into bss (fp32) ----
        for (int idx = t; idx < 32 * 64; idx += NTHREADS) {
            const int row = idx >> 6;
            const int c4  = idx & 63;
            *(float4*)&bss[row * BSS + c4 * 4] =
                *(const float4*)&g_W2T[row * 256 + c4 * 4];
        }
        __syncthreads();

        // Warp tiling: mg = voxel (0/1), ng = 64-col group (0..3)
        const int mg = warp & 1;
        const int ng = warp >> 1;
        const int arow = mg * 32 + (lane >> 2);
        const int my_num = mg ? num1 : num0;

        float acc[2][8][4];
#pragma unroll
        for (int s = 0; s < 2; s++)
#pragma unroll
            for (int i = 0; i < 8; i++)
#pragma unroll
                for (int j = 0; j < 4; j++) acc[s][i][j] = 0.0f;

        // ---- layer 2: [64x32] @ [32x256], 3xTF32 (error ~ eps^2) ----
#pragma unroll
        for (int k8 = 0; k8 < 4; k8++) {
            const int kg = k8 * 8 + (lane & 3);
            float a[8];
            a[0] = h1s[arow * H1S + kg];
            a[1] = h1s[(arow + 8) * H1S + kg];
            a[2] = h1s[arow * H1S + kg + 4];
            a[3] = h1s[(arow + 8) * H1S + kg + 4];
            a[4] = h1s[(arow + 16) * H1S + kg];
            a[5] = h1s[(arow + 24) * H1S + kg];
            a[6] = h1s[(arow + 16) * H1S + kg + 4];
            a[7] = h1s[(arow + 24) * H1S + kg + 4];
            uint32_t ah[8], al[8];
#pragma unroll
            for (int i = 0; i < 8; i++) {
                ah[i] = tf32_hi(a[i]);
                al[i] = tf32_lo(a[i], ah[i]);
            }
#pragma unroll
            for (int n8 = 0; n8 < 8; n8++) {
                const int col = ng * 64 + n8 * 8 + (lane >> 2);
                const float b0f = bss[kg * BSS + col];
                const float b1f = bss[(kg + 4) * BSS + col];
                const uint32_t bh0 = tf32_hi(b0f), bl0 = tf32_lo(b0f, bh0);
                const uint32_t bh1 = tf32_hi(b1f), bl1 = tf32_lo(b1f, bh1);
                mma_tf32(acc[0][n8], ah[0], ah[1], ah[2], ah[3], bh0, bh1);
                mma_tf32(acc[0][n8], al[0], al[1], al[2], al[3], bh0, bh1);
                mma_tf32(acc[0][n8], ah[0], ah[1], ah[2], ah[3], bl0, bl1);
                mma_tf32(acc[1][n8], ah[4], ah[5], ah[6], ah[7], bh0, bh1);
                mma_tf32(acc[1][n8], al[4], al[5], al[6], al[7], bh0, bh1);
                mma_tf32(acc[1][n8], ah[4], ah[5], ah[6], ah[7], bl0, bl1);
            }
        }
        // relu + bias, store h2 (and re-zero acc for layer 3)
#pragma unroll
        for (int n8 = 0; n8 < 8; n8++) {
            const int col = ng * 64 + n8 * 8 + (lane & 3) * 2;
            const float bb0 = b2s[col], bb1 = b2s[col + 1];
            *(float2*)&h2s[arow * H2S + col] = make_float2(
                fmaxf(acc[0][n8][0] + bb0, 0.f), fmaxf(acc[0][n8][1] + bb1, 0.f));
            *(float2*)&h2s[(arow + 8) * H2S + col] = make_float2(
                fmaxf(acc[0][n8][2] + bb0, 0.f), fmaxf(acc[0][n8][3] + bb1, 0.f));
            *(float2*)&h2s[(arow + 16) * H2S + col] = make_float2(
                fmaxf(acc[1][n8][0] + bb0, 0.f), fmaxf(acc[1][n8][1] + bb1, 0.f));
            *(float2*)&h2s[(arow + 24) * H2S + col] = make_float2(
                fmaxf(acc[1][n8][2] + bb0, 0.f), fmaxf(acc[1][n8][3] + bb1, 0.f));
#pragma unroll
            for (int j = 0; j < 4; j++) { acc[0][n8][j] = 0.f; acc[1][n8][j] = 0.f; }
        }

        // ---- layer 3: C[64][256] = h2 @ W3T, 1xTF32-RN, 8 chunks of K=32 ----
        const bool m1_live = my_num > 16;
        for (int kc = 0; kc < 8; kc++) {
            __syncthreads();   // h2s/bss producer-consumer boundary
            for (int idx = t; idx < 32 * 64; idx += NTHREADS) {
                const int row = idx >> 6;
                const int c4  = idx & 63;
                *(float4*)&bss[row * BSS + c4 * 4] =
                    *(const float4*)&g_W3T[(kc * 32 + row) * 256 + c4 * 4];
            }
            __syncthreads();

            if (my_num == 0) continue;     // dead voxel: skip all MMAs

#pragma unroll
            for (int k8 = 0; k8 < 4; k8++) {
                const int kl = k8 * 8 + (lane & 3);
                const int kg = kc * 32 + kl;
                const uint32_t a0 =
                    __float_as_uint(to_tf32_rn(h2s[arow * H2S + kg]));
                const uint32_t a1 =
                    __float_as_uint(to_tf32_rn(h2s[(arow + 8) * H2S + kg]));
                const uint32_t a2 =
                    __float_as_uint(to_tf32_rn(h2s[arow * H2S + kg + 4]));
                const uint32_t a3 =
                    __float_as_uint(to_tf32_rn(h2s[(arow + 8) * H2S + kg + 4]));
                uint32_t a4 = 0, a5 = 0, a6 = 0, a7 = 0;
                if (m1_live) {
                    a4 = __float_as_uint(to_tf32_rn(h2s[(arow + 16) * H2S + kg]));
                    a5 = __float_as_uint(to_tf32_rn(h2s[(arow + 24) * H2S + kg]));
                    a6 = __float_as_uint(to_tf32_rn(h2s[(arow + 16) * H2S + kg + 4]));
                    a7 = __float_as_uint(to_tf32_rn(h2s[(arow + 24) * H2S + kg + 4]));
                }
#pragma unroll
                for (int n8 = 0; n8 < 8; n8++) {
                    const int col = ng * 64 + n8 * 8 + (lane >> 2);
                    const uint32_t b0 = __float_as_uint(bss[kl * BSS + col]);
                    const uint32_t b1v =
                        __float_as_uint(bss[(kl + 4) * BSS + col]);
                    mma_tf32(acc[0][n8], a0, a1, a2, a3, b0, b1v);
                    if (m1_live)
                        mma_tf32(acc[1][n8], a4, a5, a6, a7, b0, b1v);
                }
            }
        }
        __syncthreads();   // all A reads done; h2s becomes C

        // ---- store C fragments into h2s ----
#pragma unroll
        for (int n8 = 0; n8 < 8; n8++) {
            const int col = ng * 64 + n8 * 8 + (lane & 3) * 2;
            *(float2*)&h2s[arow * H2S + col] =
                make_float2(acc[0][n8][0], acc[0][n8][1]);
            *(float2*)&h2s[(arow + 8) * H2S + col] =
                make_float2(acc[0][n8][2], acc[0][n8][3]);
            *(float2*)&h2s[(arow + 16) * H2S + col] =
                make_float2(acc[1][n8][0], acc[1][n8][1]);
            *(float2*)&h2s[(arow + 24) * H2S + col] =
                make_float2(acc[1][n8][2], acc[1][n8][3]);
        }
        __syncthreads();
    }

    // ---- epilogue: per-voxel masked max + b3, or zfeat for empty ----
#pragma unroll
    for (int v = 0; v < 2; v++) {
        const int nv = v ? num1 : num0;
        float r;
        if (nv == 0) {
            r = g_zfeat[t];
        } else {
            float m = -CUDART_INF_F;
            const float* c = &h2s[v * 32 * H2S + t];
            for (int p = 0; p < nv; p++) m = fmaxf(m, c[p * H2S]);
            r = m + __ldg(&b3[t]);
        }
        out[(size_t)(v0 + v) * 256 + t] = r;
    }
}

// ---------------------------------------------------------------------------
// Launch. Inputs: Frustum_Voxel, Frustum_Voxel_num, W1,b1,W2,b2,W3,b3.
// Launch period 2 -> ncu -s 5 -c 1 lands on the main kernel.
// ---------------------------------------------------------------------------
extern "C" void kernel_launch(void* const* d_in, const int* in_sizes, int n_in,
                              void* d_out, int out_size) {
    const float* fv    = (const float*)d_in[0];
    const int*   fvnum = (const int*)  d_in[1];
    const float* W1    = (const float*)d_in[2];
    const float* b1    = (const float*)d_in[3];
    const float* W2    = (const float*)d_in[4];
    const float* b2    = (const float*)d_in[5];
    const float* W3    = (const float*)d_in[6];
    const float* b3    = (const float*)d_in[7];
    float* out = (float*)d_out;

    const int V = in_sizes[1];                  // 18432 voxels (even)
    const int smem_bytes =
        (576 + 64 * H1S + 64 * H2S + 32 * BSS) * 4;   // 113,920 B

    static bool attr_set = false;
    if (!attr_set) {
        cudaFuncSetAttribute(voxel_tc_kernel,
                             cudaFuncAttributeMaxDynamicSharedMemorySize,
                             smem_bytes);
        attr_set = true;
    }

    prep_kernel<<<257, 256>>>(W2, W3, b1, b2, b3);
    voxel_tc_kernel<<<V / 2, NTHREADS, smem_bytes>>>(fv, fvnum, W1, b1, b2, b3,
                                                     out);
}